// round 3
// baseline (speedup 1.0000x reference)
#include <cuda_runtime.h>
#include <math.h>
#include <stdint.h>

// Tiling config for both GEMMs: 64x64 tile, BK=16, 256 threads, 4x4 micro-tile.
#define BM 64
#define BN 64
#define BK 16
#define TM 4
#define TN 4
#define PAD 4   // smem row padding (floats), keeps 16B alignment for float4 reads

// ---------------------------------------------------------------------------
// Kernel 1: scores[b,c,s] = sum_h W[cand[b,c],h] * x[b,s,h]  (masked -> -inf)
// ---------------------------------------------------------------------------
__global__ __launch_bounds__(256) void scores_kernel(
    const float* __restrict__ x,            // [B,S,H]
    const int* __restrict__ masks,          // [B,S]  (bool canonicalized to int32)
    const int* __restrict__ cand,           // [B,C]  (int64 canonicalized to int32)
    const float* __restrict__ w,            // [L+1,H]
    float* __restrict__ attn,               // [B,C,S]
    int B, int S, int H, int C, int Lmax)
{
    __shared__ float As[BK][BM + PAD];
    __shared__ float Bs[BK][BN + PAD];
    __shared__ const float* qrow[BM];

    const int b  = blockIdx.z;
    const int c0 = blockIdx.y * BM;
    const int s0 = blockIdx.x * BN;
    const int tid = threadIdx.x;

    if (tid < BM) {
        int c  = c0 + tid;
        int cc = c < C ? c : (C - 1);
        int lbl = cand[(size_t)b * C + cc];
        if (lbl < 0) lbl = 0;
        if (lbl > Lmax) lbl = Lmax;
        qrow[tid] = w + (size_t)lbl * H;
    }
    __syncthreads();

    const int ty = tid / 16;        // c micro-row
    const int tx = tid % 16;        // s micro-col
    const int lr = tid / 4;         // tile row for loads
    const int lk = (tid % 4) * 4;   // k offset

    const float* xb = x + ((size_t)b * S + s0) * H;

    float acc[TM][TN];
    #pragma unroll
    for (int i = 0; i < TM; i++)
        #pragma unroll
        for (int j = 0; j < TN; j++) acc[i][j] = 0.f;

    for (int k0 = 0; k0 < H; k0 += BK) {
        float4 av = *(const float4*)(qrow[lr] + k0 + lk);
        As[lk + 0][lr] = av.x; As[lk + 1][lr] = av.y;
        As[lk + 2][lr] = av.z; As[lk + 3][lr] = av.w;
        float4 bv = *(const float4*)(xb + (size_t)lr * H + k0 + lk);
        Bs[lk + 0][lr] = bv.x; Bs[lk + 1][lr] = bv.y;
        Bs[lk + 2][lr] = bv.z; Bs[lk + 3][lr] = bv.w;
        __syncthreads();

        #pragma unroll
        for (int k = 0; k < BK; k++) {
            float4 a = *(const float4*)&As[k][ty * TM];
            float4 bb = *(const float4*)&Bs[k][tx * TN];
            float av_[TM] = {a.x, a.y, a.z, a.w};
            float bv_[TN] = {bb.x, bb.y, bb.z, bb.w};
            #pragma unroll
            for (int i = 0; i < TM; i++)
                #pragma unroll
                for (int j = 0; j < TN; j++)
                    acc[i][j] += av_[i] * bv_[j];
        }
        __syncthreads();
    }

    // mask + store: masks are int32, one per position
    const int s = s0 + tx * TN;
    int4 mv = *(const int4*)(masks + (size_t)b * S + s);
    #pragma unroll
    for (int i = 0; i < TM; i++) {
        int c = c0 + ty * TM + i;
        if (c >= C) continue;
        float4 o;
        o.x = mv.x ? acc[i][0] : -INFINITY;
        o.y = mv.y ? acc[i][1] : -INFINITY;
        o.z = mv.z ? acc[i][2] : -INFINITY;
        o.w = mv.w ? acc[i][3] : -INFINITY;
        *(float4*)(attn + ((size_t)b * C + c) * S + s) = o;
    }
}

// ---------------------------------------------------------------------------
// Kernel 2: in-place softmax over the last dim (S) of attn [B*C, S].
// ---------------------------------------------------------------------------
__global__ __launch_bounds__(256) void softmax_kernel(float* __restrict__ attn, int S)
{
    const size_t row = blockIdx.x;
    float* p = attn + row * (size_t)S;
    const int tid = threadIdx.x;
    const int nvec = S / 4;

    __shared__ float red[8];

    float m = -INFINITY;
    for (int i = tid; i < nvec; i += 256) {
        float4 v = ((const float4*)p)[i];
        m = fmaxf(m, fmaxf(fmaxf(v.x, v.y), fmaxf(v.z, v.w)));
    }
    #pragma unroll
    for (int o = 16; o > 0; o >>= 1) m = fmaxf(m, __shfl_xor_sync(0xffffffffu, m, o));
    if ((tid & 31) == 0) red[tid >> 5] = m;
    __syncthreads();
    if (tid < 32) {
        float t = (tid < 8) ? red[tid] : -INFINITY;
        #pragma unroll
        for (int o = 4; o > 0; o >>= 1) t = fmaxf(t, __shfl_xor_sync(0xffffffffu, t, o));
        if (tid == 0) red[0] = t;
    }
    __syncthreads();
    m = red[0];
    __syncthreads();

    float s = 0.f;
    for (int i = tid; i < nvec; i += 256) {
        float4 v = ((const float4*)p)[i];
        v.x = __expf(v.x - m); v.y = __expf(v.y - m);
        v.z = __expf(v.z - m); v.w = __expf(v.w - m);
        s += (v.x + v.y) + (v.z + v.w);
        ((float4*)p)[i] = v;
    }
    #pragma unroll
    for (int o = 16; o > 0; o >>= 1) s += __shfl_xor_sync(0xffffffffu, s, o);
    if ((tid & 31) == 0) red[tid >> 5] = s;
    __syncthreads();
    if (tid < 32) {
        float t = (tid < 8) ? red[tid] : 0.f;
        #pragma unroll
        for (int o = 4; o > 0; o >>= 1) t += __shfl_xor_sync(0xffffffffu, t, o);
        if (tid == 0) red[0] = t;
    }
    __syncthreads();
    const float inv = 1.0f / red[0];

    for (int i = tid; i < nvec; i += 256) {
        float4 v = ((const float4*)p)[i];
        v.x *= inv; v.y *= inv; v.z *= inv; v.w *= inv;
        ((float4*)p)[i] = v;
    }
}

// ---------------------------------------------------------------------------
// Kernel 3: logits[b,c,h] = sum_s attn[b,c,s] * x[b,s,h]
// ---------------------------------------------------------------------------
__global__ __launch_bounds__(256) void logits_kernel(
    const float* __restrict__ attn,   // [B,C,S]
    const float* __restrict__ x,      // [B,S,H]
    float* __restrict__ out,          // [B,C,H]
    int B, int S, int H, int C)
{
    __shared__ float As[BK][BM + PAD];
    __shared__ float Bs[BK][BN + PAD];

    const int b  = blockIdx.z;
    const int c0 = blockIdx.y * BM;
    const int h0 = blockIdx.x * BN;
    const int tid = threadIdx.x;

    const int ty = tid / 16;
    const int tx = tid % 16;

    const int lr = tid / 4;
    const int lk = (tid % 4) * 4;
    const int bk = tid / 16;
    const int bh = (tid % 16) * 4;

    const int ca = (c0 + lr < C) ? (c0 + lr) : (C - 1);
    const float* arow = attn + ((size_t)b * C + ca) * S;
    const float* xb   = x + (size_t)b * S * H;

    float acc[TM][TN];
    #pragma unroll
    for (int i = 0; i < TM; i++)
        #pragma unroll
        for (int j = 0; j < TN; j++) acc[i][j] = 0.f;

    for (int k0 = 0; k0 < S; k0 += BK) {
        float4 av = *(const float4*)(arow + k0 + lk);
        As[lk + 0][lr] = av.x; As[lk + 1][lr] = av.y;
        As[lk + 2][lr] = av.z; As[lk + 3][lr] = av.w;
        float4 bv = *(const float4*)(xb + (size_t)(k0 + bk) * H + h0 + bh);
        *(float4*)&Bs[bk][bh] = bv;
        __syncthreads();

        #pragma unroll
        for (int k = 0; k < BK; k++) {
            float4 a = *(const float4*)&As[k][ty * TM];
            float4 bb = *(const float4*)&Bs[k][tx * TN];
            float av_[TM] = {a.x, a.y, a.z, a.w};
            float bv_[TN] = {bb.x, bb.y, bb.z, bb.w};
            #pragma unroll
            for (int i = 0; i < TM; i++)
                #pragma unroll
                for (int j = 0; j < TN; j++)
                    acc[i][j] += av_[i] * bv_[j];
        }
        __syncthreads();
    }

    const int h = h0 + tx * TN;
    #pragma unroll
    for (int i = 0; i < TM; i++) {
        int c = c0 + ty * TM + i;
        if (c >= C) continue;
        float4 o = make_float4(acc[i][0], acc[i][1], acc[i][2], acc[i][3]);
        *(float4*)(out + ((size_t)b * C + c) * H + h) = o;
    }
}

// ---------------------------------------------------------------------------
// Launch
// ---------------------------------------------------------------------------
extern "C" void kernel_launch(void* const* d_in, const int* in_sizes, int n_in,
                              void* d_out, int out_size)
{
    const float* x     = (const float*)d_in[0];   // [B,S,H]
    const int*   masks = (const int*)d_in[1];     // [B,S]  int32
    const int*   cand  = (const int*)d_in[2];     // [B,C]  int32
    const float* w     = (const float*)d_in[3];   // [L+1,H]

    const long long n0 = in_sizes[0]; // B*S*H
    const long long n1 = in_sizes[1]; // B*S
    const long long n2 = in_sizes[2]; // B*C
    const long long n3 = in_sizes[3]; // (L+1)*H

    const int H  = (int)(n0 / n1);
    const int HS = (int)((long long)out_size / n2); // H + S
    const int S  = HS - H;
    const int B  = (int)(n1 / S);
    const int C  = (int)(n2 / B);
    const int Lmax = (int)(n3 / H) - 1;

    float* logits = (float*)d_out;               // [B,C,H]
    float* attn   = logits + (size_t)B * C * H;  // [B,C,S]

    dim3 blk(256);

    dim3 g1(S / BN, (C + BM - 1) / BM, B);
    scores_kernel<<<g1, blk>>>(x, masks, cand, w, attn, B, S, H, C, Lmax);

    dim3 g2((unsigned)((size_t)B * C));
    softmax_kernel<<<g2, blk>>>(attn, S);

    dim3 g3(H / BN, (C + BM - 1) / BM, B);
    logits_kernel<<<g3, blk>>>(attn, x, logits, B, S, H, C);
}